// round 15
// baseline (speedup 1.0000x reference)
#include <cuda_runtime.h>
#include <cuda_bf16.h>
#include <math.h>
#include <stdint.h>

typedef __nv_bfloat16 bf16;
typedef __nv_bfloat162 bf162;

// ---------------- problem constants ----------------
#define Bb 4
#define Cc 512
#define NN 4096
#define GG 32
#define CPG 16

// ---------------- scratch (device globals) ----------------
__device__ __align__(128) bf16  g_h16  [(size_t)Bb*NN*Cc];    // [B,N,C] GN out
__device__ __align__(128) bf16  g_qk16 [(size_t)Bb*NN*2*Cc];  // [B,N,2C] q|k
__device__ __align__(128) bf16  g_v16  [(size_t)Bb*Cc*NN];    // [B,C,N]
__device__ __align__(128) bf16  g_ao16 [(size_t)Bb*NN*Cc];    // [B,N,C]
__device__ __align__(128) bf16  g_e16  [(size_t)Bb*NN*NN];    // [B,N,N] exp(scores)
__device__ __align__(128) bf16  g_w16  [4*Cc*Cc];             // wq|wk|wv|wo
__device__ __align__(128) float g_bqk  [2*Cc];                // bq|bk
__device__ __align__(128) float g_spart[(size_t)Bb*NN*32];    // per-CTA row partials
__device__ __align__(128) float2 g_part[Bb*GG*8];             // GN partials

// ---------------- helpers ----------------
__device__ __forceinline__ uint32_t smem_u32(const void* p) {
    uint32_t a;
    asm("{ .reg .u64 t; cvta.to.shared.u64 t, %1; cvt.u32.u64 %0, t; }" : "=r"(a) : "l"(p));
    return a;
}
__device__ __forceinline__ void gdc_wait() {
    asm volatile("griddepcontrol.wait;" ::: "memory");
}
__device__ __forceinline__ void mma_bf16(float* c, const uint32_t* a, const uint32_t* b) {
    asm volatile("mma.sync.aligned.m16n8k16.row.col.f32.bf16.bf16.f32 "
        "{%0,%1,%2,%3}, {%4,%5,%6,%7}, {%8,%9}, {%0,%1,%2,%3};"
        : "+f"(c[0]), "+f"(c[1]), "+f"(c[2]), "+f"(c[3])
        : "r"(a[0]), "r"(a[1]), "r"(a[2]), "r"(a[3]), "r"(b[0]), "r"(b[1]));
}
__device__ __forceinline__ void ldmatrix_x4(uint32_t* r, uint32_t addr) {
    asm volatile("ldmatrix.sync.aligned.m8n8.x4.shared.b16 {%0,%1,%2,%3}, [%4];"
        : "=r"(r[0]), "=r"(r[1]), "=r"(r[2]), "=r"(r[3]) : "r"(addr));
}

// ---------------- block reduction ----------------
__device__ __forceinline__ float block_sum(float v, float* sh) {
    int lane = threadIdx.x & 31, w = threadIdx.x >> 5;
    #pragma unroll
    for (int o = 16; o; o >>= 1) v += __shfl_down_sync(0xffffffffu, v, o);
    if (!lane) sh[w] = v;
    __syncthreads();
    int nw = blockDim.x >> 5;
    v = (threadIdx.x < nw) ? sh[threadIdx.x] : 0.f;
    if (w == 0) {
        #pragma unroll
        for (int o = 16; o; o >>= 1) v += __shfl_down_sync(0xffffffffu, v, o);
        if (!lane) sh[0] = v;
    }
    __syncthreads();
    float r = sh[0]; __syncthreads(); return r;
}

// ---------------- GroupNorm stage 1 --------------------------
__global__ __launch_bounds__(256) void gn_stats(
    const float* __restrict__ x, float2* __restrict__ partials)
{
    __shared__ float sh[32];
    int blk = blockIdx.x;
    int bg = blk >> 3, p = blk & 7;
    const size_t base = (size_t)bg * CPG * NN;
    const int i0 = p * 512;

    float s = 0.f, ss = 0.f;
    #pragma unroll
    for (int c = 0; c < CPG; c++) {
        #pragma unroll
        for (int j = 0; j < 2; j++) {
            float v = x[base + (size_t)c * NN + i0 + threadIdx.x + j * 256];
            s += v; ss += v * v;
        }
    }
    s  = block_sum(s,  sh);
    ss = block_sum(ss, sh);
    if (threadIdx.x == 0) partials[blk] = make_float2(s, ss);
}

// ---------------- GroupNorm stage 2 (PDL: waits on gn_stats) ----------------
__global__ __launch_bounds__(256) void gn_norm(
    const float* __restrict__ x, const float2* __restrict__ partials,
    const float* __restrict__ gamma, const float* __restrict__ beta,
    bf16* __restrict__ hT)
{
    gdc_wait();

    int blk = blockIdx.x;
    int bg = blk >> 3, p = blk & 7;
    int b = bg / GG, g = bg % GG;

    float s = 0.f, ss = 0.f;
    #pragma unroll
    for (int q = 0; q < 8; q++) {
        float2 pr = partials[bg * 8 + q];
        s += pr.x; ss += pr.y;
    }
    const float len = (float)(CPG * NN);
    float mean = s / len;
    float inv  = rsqrtf(ss / len - mean * mean + 1e-6f);

    float gm[CPG], bt[CPG];
    #pragma unroll
    for (int c = 0; c < CPG; c++) { gm[c] = gamma[g*CPG+c] * inv; bt[c] = beta[g*CPG+c]; }

    const size_t base = (size_t)bg * CPG * NN;
    #pragma unroll
    for (int j = 0; j < 2; j++) {
        int i = p * 512 + threadIdx.x + j * 256;
        bf162 vals[CPG/2];
        #pragma unroll
        for (int c = 0; c < CPG; c += 2) {
            float a  = (x[base + (size_t)c     * NN + i] - mean) * gm[c]   + bt[c];
            float b2 = (x[base + (size_t)(c+1) * NN + i] - mean) * gm[c+1] + bt[c+1];
            vals[c/2] = __floats2bfloat162_rn(a, b2);
        }
        bf16* dst = hT + ((size_t)b * NN + i) * Cc + g * CPG;
        #pragma unroll
        for (int q = 0; q < CPG/8; q++)
            ((float4*)dst)[q] = *(float4*)&vals[q*4];
    }
}

// ---------------- weight convert + bias concat ----------------
__global__ __launch_bounds__(256) void prep_kernel(
    const float* __restrict__ a, const float* __restrict__ b,
    const float* __restrict__ c, const float* __restrict__ d,
    bf16* __restrict__ o,
    const float* __restrict__ bq, const float* __restrict__ bk,
    float* __restrict__ bqk)
{
    int i = blockIdx.x * 256 + threadIdx.x;
    int w = i >> 18, j = i & 0x3FFFF;
    const float* src = (w == 0) ? a : (w == 1) ? b : (w == 2) ? c : d;
    o[i] = __float2bfloat16_rn(src[j]);
    if (i < 2 * Cc) bqk[i] = (i < Cc) ? bq[i] : bk[i - Cc];
}

// ---------------- bf16 mma.sync GEMM ----------
// EPI: 0 = +bias[n] -> bf16       (merged QK proj)
//      1 = +bias[m] -> bf16       (V proj)
//      2 = exp(v*alpha) -> bf16 + per-CTA row partials -> spart (scores)
//      3 = *invsum[m] -> bf16     (attn*V; invsum computed in-kernel; PDL wait)
//      4 = +bias[m]+res fp32      (output proj + residual; PDL wait)
#define BM 128
#define BN 128
#define BK 64
#define STAGES 3
#define SROW 72
#define ATILE_H (BM * SROW)
#define BTILE_H (BN * SROW)
#define STAGE_H (ATILE_H + BTILE_H)
#define STAGE_BYTES (STAGE_H * 2)
#define SMEM_REQ (STAGES * STAGE_BYTES + 512)

template<int ROWS>
__device__ __forceinline__ void load_tile(const bf16* g, bf16* s, int tid, int ld) {
    int ch = tid & 7;
    int r0 = tid >> 3;
    #pragma unroll
    for (int i = 0; i < ROWS / 32; i++) {
        int r = r0 + i * 32;
        uint32_t dst = smem_u32(s + r * SROW + ch * 8);
        const bf16* src = g + (size_t)r * ld + ch * 8;
        asm volatile("cp.async.cg.shared.global [%0], [%1], 16;" :: "r"(dst), "l"(src));
    }
}

template<int EPI>
__global__ __launch_bounds__(256, 2) void mma_gemm(
    const bf16* __restrict__ A, long zA, int ldA,
    const bf16* __restrict__ B, long zB, int ldB,
    const float* __restrict__ bias, long zBias,
    const float* __restrict__ res, long zR,
    float* __restrict__ spart,
    void* __restrict__ Cout, long zC, int ldC,
    int K, float alpha)
{
    constexpr bool OUT_BF = (EPI != 4);
    extern __shared__ bf16 smem[];
    float* srsum = (float*)(smem + STAGES * STAGE_H);

    if (EPI == 3 || EPI == 4) gdc_wait();   // PDL: predecessor complete + visible

    const int tid = threadIdx.x;
    const int m0 = blockIdx.y * BM, n0 = blockIdx.x * BN, bz = blockIdx.z;

    A += (size_t)bz * zA + (size_t)m0 * ldA;
    B += (size_t)bz * zB + (size_t)n0 * ldB;
    if (EPI == 1 || EPI == 4) bias += (size_t)bz * zBias;

    const int KT = K / BK;

    #pragma unroll
    for (int st = 0; st < STAGES - 1; st++) {
        load_tile<BM>(A + st * BK, smem + st * STAGE_H, tid, ldA);
        load_tile<BN>(B + st * BK, smem + st * STAGE_H + ATILE_H, tid, ldB);
        asm volatile("cp.async.commit_group;" ::: "memory");
    }

    // EPI3: fixed-order inverse row-sums from spart (overlaps the fills).
    if (EPI == 3) {
        if (tid < 128) {
            const float* p = spart + ((size_t)bz * NN + m0 + tid) * 32;
            float s = 0.f;
            #pragma unroll
            for (int t = 0; t < 32; t++) s += p[t];
            srsum[tid] = 1.f / s;
        }
    }

    const int lane = tid & 31, wid = tid >> 5;
    const int gid = lane >> 2, tig = lane & 3;
    const int wm = (wid & 1) * 64;
    const int wn = (wid >> 1) * 32;

    const uint32_t sbase = smem_u32(smem);
    const uint32_t a_off = ((wm + (lane & 15)) * SROW + ((lane >> 4) * 8)) * 2;
    const uint32_t b_off = (ATILE_H + (wn + (lane & 7) + ((lane >> 4) << 3)) * SROW
                            + (((lane >> 3) & 1) * 8)) * 2;

    float c[4][4][4];
    #pragma unroll
    for (int im = 0; im < 4; im++)
        #pragma unroll
        for (int in = 0; in < 4; in++)
            #pragma unroll
            for (int r = 0; r < 4; r++) c[im][in][r] = 0.f;

    uint32_t af[2][4][4], bq[2][2][4];

    for (int kt = 0; kt < KT; kt++) {
        asm volatile("cp.async.wait_group %0;" :: "n"(STAGES - 2) : "memory");
        __syncthreads();

        if (kt + STAGES - 1 < KT) {
            int st = (kt + STAGES - 1) % STAGES;
            load_tile<BM>(A + (kt + STAGES - 1) * BK, smem + st * STAGE_H, tid, ldA);
            load_tile<BN>(B + (kt + STAGES - 1) * BK, smem + st * STAGE_H + ATILE_H, tid, ldB);
        }
        asm volatile("cp.async.commit_group;" ::: "memory");

        const uint32_t stb = sbase + (kt % STAGES) * STAGE_BYTES;

        #pragma unroll
        for (int im = 0; im < 4; im++)
            ldmatrix_x4(af[0][im], stb + a_off + im * (16 * SROW * 2));
        #pragma unroll
        for (int ib = 0; ib < 2; ib++)
            ldmatrix_x4(bq[0][ib], stb + b_off + ib * (16 * SROW * 2));

        #pragma unroll
        for (int kk = 0; kk < 4; kk++) {
            int cur = kk & 1, nxt = cur ^ 1;
            if (kk < 3) {
                const uint32_t ka = stb + (kk + 1) * 32;
                #pragma unroll
                for (int im = 0; im < 4; im++)
                    ldmatrix_x4(af[nxt][im], ka + a_off + im * (16 * SROW * 2));
                #pragma unroll
                for (int ib = 0; ib < 2; ib++)
                    ldmatrix_x4(bq[nxt][ib], ka + b_off + ib * (16 * SROW * 2));
            }
            #pragma unroll
            for (int im = 0; im < 4; im++)
                #pragma unroll
                for (int in = 0; in < 4; in++)
                    mma_bf16(c[im][in], af[cur][im], &bq[cur][in >> 1][(in & 1) * 2]);
        }
    }

    // ---- epilogue ----
    float rs[4][2];
    if (EPI == 2) {
        #pragma unroll
        for (int im = 0; im < 4; im++) { rs[im][0] = 0.f; rs[im][1] = 0.f; }
    }

    #pragma unroll
    for (int im = 0; im < 4; im++) {
        int r0 = im * 16 + gid;
        float bm0 = 0.f, bm1 = 0.f;
        if (EPI == 1 || EPI == 4) {
            bm0 = __ldg(bias + m0 + wm + r0);
            bm1 = __ldg(bias + m0 + wm + r0 + 8);
        } else if (EPI == 3) {
            bm0 = srsum[wm + r0];
            bm1 = srsum[wm + r0 + 8];
        }
        #pragma unroll
        for (int in = 0; in < 4; in++) {
            int col = in * 8 + tig * 2;
            float v0 = c[im][in][0], v1 = c[im][in][1];
            float v2 = c[im][in][2], v3 = c[im][in][3];
            if (EPI == 0) {
                float bn0 = __ldg(bias + n0 + wn + col);
                float bn1 = __ldg(bias + n0 + wn + col + 1);
                v0 += bn0; v1 += bn1; v2 += bn0; v3 += bn1;
            } else if (EPI == 1) {
                v0 += bm0; v1 += bm0; v2 += bm1; v3 += bm1;
            } else if (EPI == 2) {
                v0 = __expf(v0 * alpha); v1 = __expf(v1 * alpha);
                v2 = __expf(v2 * alpha); v3 = __expf(v3 * alpha);
                rs[im][0] += v0 + v1;
                rs[im][1] += v2 + v3;
            } else if (EPI == 3) {
                v0 *= bm0; v1 *= bm0; v2 *= bm1; v3 *= bm1;
            } else if (EPI == 4) {
                const float* ra = res + (size_t)bz * zR + (size_t)(m0 + wm + r0) * ldC + n0 + wn + col;
                const float* rb = res + (size_t)bz * zR + (size_t)(m0 + wm + r0 + 8) * ldC + n0 + wn + col;
                v0 += bm0 + ra[0]; v1 += bm0 + ra[1];
                v2 += bm1 + rb[0]; v3 += bm1 + rb[1];
            }
            if (OUT_BF) {
                bf16* Cb = (bf16*)Cout + (size_t)bz * zC + (size_t)(m0 + wm + r0) * ldC + n0 + wn + col;
                bf16* Cb2 = (bf16*)Cout + (size_t)bz * zC + (size_t)(m0 + wm + r0 + 8) * ldC + n0 + wn + col;
                *(bf162*)Cb  = __floats2bfloat162_rn(v0, v1);
                *(bf162*)Cb2 = __floats2bfloat162_rn(v2, v3);
            } else {
                float* Cf = (float*)Cout + (size_t)bz * zC + (size_t)(m0 + wm + r0) * ldC + n0 + wn + col;
                float* Cf2 = (float*)Cout + (size_t)bz * zC + (size_t)(m0 + wm + r0 + 8) * ldC + n0 + wn + col;
                *(float2*)Cf  = make_float2(v0, v1);
                *(float2*)Cf2 = make_float2(v2, v3);
            }
        }
    }

    // ---- EPI2: deterministic per-CTA row-sum reduction -> spart ----
    if (EPI == 2) {
        __syncthreads();
        float* srow = (float*)smem;
        const int nwIdx = wid >> 1;
        #pragma unroll
        for (int im = 0; im < 4; im++) {
            #pragma unroll
            for (int h = 0; h < 2; h++) {
                float v = rs[im][h];
                v += __shfl_xor_sync(0xffffffffu, v, 1);
                v += __shfl_xor_sync(0xffffffffu, v, 2);
                if (tig == 0)
                    srow[nwIdx * 128 + wm + im * 16 + gid + h * 8] = v;
            }
        }
        __syncthreads();
        if (tid < 128) {
            float t = srow[tid] + srow[128 + tid] + srow[256 + tid] + srow[384 + tid];
            spart[((size_t)bz * NN + m0 + tid) * 32 + blockIdx.x] = t;
        }
    }
}

// ---------------- launch ----------------
extern "C" void kernel_launch(void* const* d_in, const int* in_sizes, int n_in,
                              void* d_out, int out_size)
{
    const float* x     = (const float*)d_in[0];
    const float* gamma = (const float*)d_in[1];
    const float* beta  = (const float*)d_in[2];
    const float* wq    = (const float*)d_in[3];
    const float* bq    = (const float*)d_in[4];
    const float* wk    = (const float*)d_in[5];
    const float* bk    = (const float*)d_in[6];
    const float* wv    = (const float*)d_in[7];
    const float* bv    = (const float*)d_in[8];
    const float* wo    = (const float*)d_in[9];
    const float* bo    = (const float*)d_in[10];
    float* out = (float*)d_out;

    bf16 *h16, *qk16, *v16, *ao16, *e16, *w16;
    float *bqk, *spart;
    float2* part;
    cudaGetSymbolAddress((void**)&h16,  g_h16);
    cudaGetSymbolAddress((void**)&qk16, g_qk16);
    cudaGetSymbolAddress((void**)&v16,  g_v16);
    cudaGetSymbolAddress((void**)&ao16, g_ao16);
    cudaGetSymbolAddress((void**)&e16,  g_e16);
    cudaGetSymbolAddress((void**)&w16,  g_w16);
    cudaGetSymbolAddress((void**)&bqk,  g_bqk);
    cudaGetSymbolAddress((void**)&spart, g_spart);
    cudaGetSymbolAddress((void**)&part, g_part);

    static bool attr_done = false;
    if (!attr_done) {
        cudaFuncSetAttribute(mma_gemm<0>, cudaFuncAttributeMaxDynamicSharedMemorySize, SMEM_REQ);
        cudaFuncSetAttribute(mma_gemm<1>, cudaFuncAttributeMaxDynamicSharedMemorySize, SMEM_REQ);
        cudaFuncSetAttribute(mma_gemm<2>, cudaFuncAttributeMaxDynamicSharedMemorySize, SMEM_REQ);
        cudaFuncSetAttribute(mma_gemm<3>, cudaFuncAttributeMaxDynamicSharedMemorySize, SMEM_REQ);
        cudaFuncSetAttribute(mma_gemm<4>, cudaFuncAttributeMaxDynamicSharedMemorySize, SMEM_REQ);
        attr_done = true;
    }

    const long CN  = (long)Cc * NN;
    const long NC  = (long)NN * Cc;
    const long NC2 = (long)NN * 2 * Cc;
    const long NN2 = (long)NN * NN;
    const float scale = 1.0f / sqrtf((float)Cc);

    cudaLaunchAttribute pdl[1];
    pdl[0].id = cudaLaunchAttributeProgrammaticStreamSerialization;
    pdl[0].val.programmaticStreamSerializationAllowed = 1;

    // 1) prep first (depends only on inputs)
    prep_kernel<<<4 * Cc * Cc / 256, 256>>>(wq, wk, wv, wo, w16, bq, bk, bqk);

    // 2) gn_stats — independent of prep, PDL (no wait): drain-fill overlap
    {
        cudaLaunchConfig_t cfg = {};
        cfg.gridDim = dim3(Bb * GG * 8);
        cfg.blockDim = dim3(256);
        cfg.stream = 0;
        cfg.attrs = pdl; cfg.numAttrs = 1;
        cudaLaunchKernelEx(&cfg, gn_stats, x, part);
    }

    // 3) gn_norm — depends on gn_stats, PDL + in-kernel gdc_wait
    {
        cudaLaunchConfig_t cfg = {};
        cfg.gridDim = dim3(Bb * GG * 8);
        cfg.blockDim = dim3(256);
        cfg.stream = 0;
        cfg.attrs = pdl; cfg.numAttrs = 1;
        cudaLaunchKernelEx(&cfg, gn_norm, x, (const float2*)part, gamma, beta, h16);
    }

    // 4) merged QK proj — multi-predecessor (gn_norm + prep): normal launch
    mma_gemm<0><<<dim3(2*Cc/BN, NN/BM, Bb), 256, SMEM_REQ>>>(
        h16, NC, Cc, w16, 0, Cc, bqk, 0, nullptr, 0, nullptr, qk16, NC2, 2*Cc, Cc, 0.f);

    // 5) V proj — independent of QK proj: PDL (no wait)
    {
        cudaLaunchConfig_t cfg = {};
        cfg.gridDim = dim3(NN/BN, Cc/BM, Bb);
        cfg.blockDim = dim3(256);
        cfg.dynamicSmemBytes = SMEM_REQ;
        cfg.stream = 0;
        cfg.attrs = pdl; cfg.numAttrs = 1;
        cudaLaunchKernelEx(&cfg, mma_gemm<1>,
            (const bf16*)(w16 + 2*Cc*Cc), 0L, (int)Cc,
            (const bf16*)h16, NC, (int)Cc,
            bv, 0L, (const float*)nullptr, 0L, (float*)nullptr,
            (void*)v16, CN, (int)NN, (int)Cc, 0.f);
    }

    // 6) exp-scores — depends on gemm0 two launches back: normal launch
    mma_gemm<2><<<dim3(NN/BN, NN/BM, Bb), 256, SMEM_REQ>>>(
        qk16, NC2, 2*Cc, qk16 + Cc, NC2, 2*Cc, nullptr, 0, nullptr, 0, spart, e16, NN2, NN, Cc, scale);

    // 7) attn*V — single predecessor (gemm2): PDL + in-kernel gdc_wait
    {
        cudaLaunchConfig_t cfg = {};
        cfg.gridDim = dim3(Cc/BN, NN/BM, Bb);
        cfg.blockDim = dim3(256);
        cfg.dynamicSmemBytes = SMEM_REQ;
        cfg.stream = 0;
        cfg.attrs = pdl; cfg.numAttrs = 1;
        cudaLaunchKernelEx(&cfg, mma_gemm<3>,
            (const bf16*)e16, NN2, (int)NN,
            (const bf16*)v16, CN, (int)NN,
            (const float*)nullptr, 0L, (const float*)nullptr, 0L, spart,
            (void*)ao16, NC, (int)Cc, (int)NN, 0.f);
    }

    // 8) output proj + residual — single predecessor (gemm3): PDL + gdc_wait
    {
        cudaLaunchConfig_t cfg = {};
        cfg.gridDim = dim3(NN/BN, Cc/BM, Bb);
        cfg.blockDim = dim3(256);
        cfg.dynamicSmemBytes = SMEM_REQ;
        cfg.stream = 0;
        cfg.attrs = pdl; cfg.numAttrs = 1;
        cudaLaunchKernelEx(&cfg, mma_gemm<4>,
            (const bf16*)(w16 + 3*Cc*Cc), 0L, (int)Cc,
            (const bf16*)ao16, NC, (int)Cc,
            bo, 0L, x, CN, (float*)nullptr,
            (void*)out, CN, (int)NN, (int)Cc, 0.f);
    }
}

// round 16
// speedup vs baseline: 1.0026x; 1.0026x over previous
#include <cuda_runtime.h>
#include <cuda_bf16.h>
#include <math.h>
#include <stdint.h>

typedef __nv_bfloat16 bf16;
typedef __nv_bfloat162 bf162;

// ---------------- problem constants ----------------
#define Bb 4
#define Cc 512
#define NN 4096
#define GG 32
#define CPG 16

// ---------------- scratch (device globals) ----------------
__device__ __align__(128) bf16  g_h16  [(size_t)Bb*NN*Cc];    // [B,N,C] GN out
__device__ __align__(128) bf16  g_qk16 [(size_t)Bb*NN*2*Cc];  // [B,N,2C] q|k
__device__ __align__(128) bf16  g_v16  [(size_t)Bb*Cc*NN];    // [B,C,N]
__device__ __align__(128) bf16  g_ao16 [(size_t)Bb*NN*Cc];    // [B,N,C]
__device__ __align__(128) bf16  g_e16  [(size_t)Bb*NN*NN];    // [B,N,N] exp(scores)
__device__ __align__(128) bf16  g_w16  [4*Cc*Cc];             // wq|wk|wv|wo
__device__ __align__(128) float g_bqk  [2*Cc];                // bq|bk
__device__ __align__(128) float g_spart[(size_t)Bb*NN*32];    // per-CTA row partials
__device__ __align__(128) float2 g_part[Bb*GG*8];             // GN partials

// ---------------- helpers ----------------
__device__ __forceinline__ uint32_t smem_u32(const void* p) {
    uint32_t a;
    asm("{ .reg .u64 t; cvta.to.shared.u64 t, %1; cvt.u32.u64 %0, t; }" : "=r"(a) : "l"(p));
    return a;
}
__device__ __forceinline__ void gdc_wait() {
    asm volatile("griddepcontrol.wait;" ::: "memory");
}
__device__ __forceinline__ void mma_bf16(float* c, const uint32_t* a, const uint32_t* b) {
    asm volatile("mma.sync.aligned.m16n8k16.row.col.f32.bf16.bf16.f32 "
        "{%0,%1,%2,%3}, {%4,%5,%6,%7}, {%8,%9}, {%0,%1,%2,%3};"
        : "+f"(c[0]), "+f"(c[1]), "+f"(c[2]), "+f"(c[3])
        : "r"(a[0]), "r"(a[1]), "r"(a[2]), "r"(a[3]), "r"(b[0]), "r"(b[1]));
}
__device__ __forceinline__ void ldmatrix_x4(uint32_t* r, uint32_t addr) {
    asm volatile("ldmatrix.sync.aligned.m8n8.x4.shared.b16 {%0,%1,%2,%3}, [%4];"
        : "=r"(r[0]), "=r"(r[1]), "=r"(r[2]), "=r"(r[3]) : "r"(addr));
}

// ---------------- block reduction ----------------
__device__ __forceinline__ float block_sum(float v, float* sh) {
    int lane = threadIdx.x & 31, w = threadIdx.x >> 5;
    #pragma unroll
    for (int o = 16; o; o >>= 1) v += __shfl_down_sync(0xffffffffu, v, o);
    if (!lane) sh[w] = v;
    __syncthreads();
    int nw = blockDim.x >> 5;
    v = (threadIdx.x < nw) ? sh[threadIdx.x] : 0.f;
    if (w == 0) {
        #pragma unroll
        for (int o = 16; o; o >>= 1) v += __shfl_down_sync(0xffffffffu, v, o);
        if (!lane) sh[0] = v;
    }
    __syncthreads();
    float r = sh[0]; __syncthreads(); return r;
}

// ---------------- GroupNorm stage 1 --------------------------
__global__ __launch_bounds__(256) void gn_stats(
    const float* __restrict__ x, float2* __restrict__ partials)
{
    __shared__ float sh[32];
    int blk = blockIdx.x;
    int bg = blk >> 3, p = blk & 7;
    const size_t base = (size_t)bg * CPG * NN;
    const int i0 = p * 512;

    float s = 0.f, ss = 0.f;
    #pragma unroll
    for (int c = 0; c < CPG; c++) {
        #pragma unroll
        for (int j = 0; j < 2; j++) {
            float v = x[base + (size_t)c * NN + i0 + threadIdx.x + j * 256];
            s += v; ss += v * v;
        }
    }
    s  = block_sum(s,  sh);
    ss = block_sum(ss, sh);
    if (threadIdx.x == 0) partials[blk] = make_float2(s, ss);
}

// ---------------- GroupNorm stage 2 (PDL: waits on gn_stats) ----------------
__global__ __launch_bounds__(256) void gn_norm(
    const float* __restrict__ x, const float2* __restrict__ partials,
    const float* __restrict__ gamma, const float* __restrict__ beta,
    bf16* __restrict__ hT)
{
    gdc_wait();

    int blk = blockIdx.x;
    int bg = blk >> 3, p = blk & 7;
    int b = bg / GG, g = bg % GG;

    float s = 0.f, ss = 0.f;
    #pragma unroll
    for (int q = 0; q < 8; q++) {
        float2 pr = partials[bg * 8 + q];
        s += pr.x; ss += pr.y;
    }
    const float len = (float)(CPG * NN);
    float mean = s / len;
    float inv  = rsqrtf(ss / len - mean * mean + 1e-6f);

    float gm[CPG], bt[CPG];
    #pragma unroll
    for (int c = 0; c < CPG; c++) { gm[c] = gamma[g*CPG+c] * inv; bt[c] = beta[g*CPG+c]; }

    const size_t base = (size_t)bg * CPG * NN;
    #pragma unroll
    for (int j = 0; j < 2; j++) {
        int i = p * 512 + threadIdx.x + j * 256;
        bf162 vals[CPG/2];
        #pragma unroll
        for (int c = 0; c < CPG; c += 2) {
            float a  = (x[base + (size_t)c     * NN + i] - mean) * gm[c]   + bt[c];
            float b2 = (x[base + (size_t)(c+1) * NN + i] - mean) * gm[c+1] + bt[c+1];
            vals[c/2] = __floats2bfloat162_rn(a, b2);
        }
        bf16* dst = hT + ((size_t)b * NN + i) * Cc + g * CPG;
        #pragma unroll
        for (int q = 0; q < CPG/8; q++)
            ((float4*)dst)[q] = *(float4*)&vals[q*4];
    }
}

// ---------------- weight convert + bias concat ----------------
__global__ __launch_bounds__(256) void prep_kernel(
    const float* __restrict__ a, const float* __restrict__ b,
    const float* __restrict__ c, const float* __restrict__ d,
    bf16* __restrict__ o,
    const float* __restrict__ bq, const float* __restrict__ bk,
    float* __restrict__ bqk)
{
    int i = blockIdx.x * 256 + threadIdx.x;
    int w = i >> 18, j = i & 0x3FFFF;
    const float* src = (w == 0) ? a : (w == 1) ? b : (w == 2) ? c : d;
    o[i] = __float2bfloat16_rn(src[j]);
    if (i < 2 * Cc) bqk[i] = (i < Cc) ? bq[i] : bk[i - Cc];
}

// ---------------- bf16 mma.sync GEMM ----------
// EPI: 0 = +bias[n] -> bf16       (merged QK proj)
//      1 = +bias[m] -> bf16       (V proj)
//      2 = exp(v*alpha) -> bf16 + per-CTA row partials -> spart (scores)
//      3 = *invsum[m] -> bf16     (attn*V; invsum computed in-kernel; PDL wait)
//      4 = +bias[m]+res fp32      (output proj + residual; PDL wait)
#define BM 128
#define BN 128
#define BK 64
#define STAGES 3
#define SROW 72
#define ATILE_H (BM * SROW)
#define BTILE_H (BN * SROW)
#define STAGE_H (ATILE_H + BTILE_H)
#define STAGE_BYTES (STAGE_H * 2)
#define SMEM_REQ (STAGES * STAGE_BYTES + 512)

template<int ROWS>
__device__ __forceinline__ void load_tile(const bf16* g, bf16* s, int tid, int ld) {
    int ch = tid & 7;
    int r0 = tid >> 3;
    #pragma unroll
    for (int i = 0; i < ROWS / 32; i++) {
        int r = r0 + i * 32;
        uint32_t dst = smem_u32(s + r * SROW + ch * 8);
        const bf16* src = g + (size_t)r * ld + ch * 8;
        asm volatile("cp.async.cg.shared.global [%0], [%1], 16;" :: "r"(dst), "l"(src));
    }
}

template<int EPI>
__global__ __launch_bounds__(256, 2) void mma_gemm(
    const bf16* __restrict__ A, long zA, int ldA,
    const bf16* __restrict__ B, long zB, int ldB,
    const float* __restrict__ bias, long zBias,
    const float* __restrict__ res, long zR,
    float* __restrict__ spart,
    void* __restrict__ Cout, long zC, int ldC,
    int K, float alpha)
{
    constexpr bool OUT_BF = (EPI != 4);
    extern __shared__ bf16 smem[];
    float* srsum = (float*)(smem + STAGES * STAGE_H);

    if (EPI == 3 || EPI == 4) gdc_wait();   // PDL: predecessor complete + visible

    const int tid = threadIdx.x;
    const int m0 = blockIdx.y * BM, n0 = blockIdx.x * BN, bz = blockIdx.z;

    A += (size_t)bz * zA + (size_t)m0 * ldA;
    B += (size_t)bz * zB + (size_t)n0 * ldB;
    if (EPI == 1 || EPI == 4) bias += (size_t)bz * zBias;

    const int KT = K / BK;

    #pragma unroll
    for (int st = 0; st < STAGES - 1; st++) {
        load_tile<BM>(A + st * BK, smem + st * STAGE_H, tid, ldA);
        load_tile<BN>(B + st * BK, smem + st * STAGE_H + ATILE_H, tid, ldB);
        asm volatile("cp.async.commit_group;" ::: "memory");
    }

    // EPI3: fixed-order inverse row-sums from spart (overlaps the fills).
    if (EPI == 3) {
        if (tid < 128) {
            const float* p = spart + ((size_t)bz * NN + m0 + tid) * 32;
            float s = 0.f;
            #pragma unroll
            for (int t = 0; t < 32; t++) s += p[t];
            srsum[tid] = 1.f / s;
        }
    }

    const int lane = tid & 31, wid = tid >> 5;
    const int gid = lane >> 2, tig = lane & 3;
    const int wm = (wid & 1) * 64;
    const int wn = (wid >> 1) * 32;

    const uint32_t sbase = smem_u32(smem);
    const uint32_t a_off = ((wm + (lane & 15)) * SROW + ((lane >> 4) * 8)) * 2;
    const uint32_t b_off = (ATILE_H + (wn + (lane & 7) + ((lane >> 4) << 3)) * SROW
                            + (((lane >> 3) & 1) * 8)) * 2;

    float c[4][4][4];
    #pragma unroll
    for (int im = 0; im < 4; im++)
        #pragma unroll
        for (int in = 0; in < 4; in++)
            #pragma unroll
            for (int r = 0; r < 4; r++) c[im][in][r] = 0.f;

    uint32_t af[2][4][4], bq[2][2][4];

    for (int kt = 0; kt < KT; kt++) {
        asm volatile("cp.async.wait_group %0;" :: "n"(STAGES - 2) : "memory");
        __syncthreads();

        if (kt + STAGES - 1 < KT) {
            int st = (kt + STAGES - 1) % STAGES;
            load_tile<BM>(A + (kt + STAGES - 1) * BK, smem + st * STAGE_H, tid, ldA);
            load_tile<BN>(B + (kt + STAGES - 1) * BK, smem + st * STAGE_H + ATILE_H, tid, ldB);
        }
        asm volatile("cp.async.commit_group;" ::: "memory");

        const uint32_t stb = sbase + (kt % STAGES) * STAGE_BYTES;

        #pragma unroll
        for (int im = 0; im < 4; im++)
            ldmatrix_x4(af[0][im], stb + a_off + im * (16 * SROW * 2));
        #pragma unroll
        for (int ib = 0; ib < 2; ib++)
            ldmatrix_x4(bq[0][ib], stb + b_off + ib * (16 * SROW * 2));

        #pragma unroll
        for (int kk = 0; kk < 4; kk++) {
            int cur = kk & 1, nxt = cur ^ 1;
            if (kk < 3) {
                const uint32_t ka = stb + (kk + 1) * 32;
                #pragma unroll
                for (int im = 0; im < 4; im++)
                    ldmatrix_x4(af[nxt][im], ka + a_off + im * (16 * SROW * 2));
                #pragma unroll
                for (int ib = 0; ib < 2; ib++)
                    ldmatrix_x4(bq[nxt][ib], ka + b_off + ib * (16 * SROW * 2));
            }
            #pragma unroll
            for (int im = 0; im < 4; im++)
                #pragma unroll
                for (int in = 0; in < 4; in++)
                    mma_bf16(c[im][in], af[cur][im], &bq[cur][in >> 1][(in & 1) * 2]);
        }
    }

    // ---- epilogue ----
    float rs[4][2];
    if (EPI == 2) {
        #pragma unroll
        for (int im = 0; im < 4; im++) { rs[im][0] = 0.f; rs[im][1] = 0.f; }
    }

    #pragma unroll
    for (int im = 0; im < 4; im++) {
        int r0 = im * 16 + gid;
        float bm0 = 0.f, bm1 = 0.f;
        if (EPI == 1 || EPI == 4) {
            bm0 = __ldg(bias + m0 + wm + r0);
            bm1 = __ldg(bias + m0 + wm + r0 + 8);
        } else if (EPI == 3) {
            bm0 = srsum[wm + r0];
            bm1 = srsum[wm + r0 + 8];
        }
        #pragma unroll
        for (int in = 0; in < 4; in++) {
            int col = in * 8 + tig * 2;
            float v0 = c[im][in][0], v1 = c[im][in][1];
            float v2 = c[im][in][2], v3 = c[im][in][3];
            if (EPI == 0) {
                float bn0 = __ldg(bias + n0 + wn + col);
                float bn1 = __ldg(bias + n0 + wn + col + 1);
                v0 += bn0; v1 += bn1; v2 += bn0; v3 += bn1;
            } else if (EPI == 1) {
                v0 += bm0; v1 += bm0; v2 += bm1; v3 += bm1;
            } else if (EPI == 2) {
                v0 = __expf(v0 * alpha); v1 = __expf(v1 * alpha);
                v2 = __expf(v2 * alpha); v3 = __expf(v3 * alpha);
                rs[im][0] += v0 + v1;
                rs[im][1] += v2 + v3;
            } else if (EPI == 3) {
                v0 *= bm0; v1 *= bm0; v2 *= bm1; v3 *= bm1;
            } else if (EPI == 4) {
                const float* ra = res + (size_t)bz * zR + (size_t)(m0 + wm + r0) * ldC + n0 + wn + col;
                const float* rb = res + (size_t)bz * zR + (size_t)(m0 + wm + r0 + 8) * ldC + n0 + wn + col;
                v0 += bm0 + ra[0]; v1 += bm0 + ra[1];
                v2 += bm1 + rb[0]; v3 += bm1 + rb[1];
            }
            if (OUT_BF) {
                bf16* Cb = (bf16*)Cout + (size_t)bz * zC + (size_t)(m0 + wm + r0) * ldC + n0 + wn + col;
                bf16* Cb2 = (bf16*)Cout + (size_t)bz * zC + (size_t)(m0 + wm + r0 + 8) * ldC + n0 + wn + col;
                *(bf162*)Cb  = __floats2bfloat162_rn(v0, v1);
                *(bf162*)Cb2 = __floats2bfloat162_rn(v2, v3);
            } else {
                float* Cf = (float*)Cout + (size_t)bz * zC + (size_t)(m0 + wm + r0) * ldC + n0 + wn + col;
                float* Cf2 = (float*)Cout + (size_t)bz * zC + (size_t)(m0 + wm + r0 + 8) * ldC + n0 + wn + col;
                *(float2*)Cf  = make_float2(v0, v1);
                *(float2*)Cf2 = make_float2(v2, v3);
            }
        }
    }

    // ---- EPI2: deterministic per-CTA row-sum reduction -> spart ----
    if (EPI == 2) {
        __syncthreads();
        float* srow = (float*)smem;
        const int nwIdx = wid >> 1;
        #pragma unroll
        for (int im = 0; im < 4; im++) {
            #pragma unroll
            for (int h = 0; h < 2; h++) {
                float v = rs[im][h];
                v += __shfl_xor_sync(0xffffffffu, v, 1);
                v += __shfl_xor_sync(0xffffffffu, v, 2);
                if (tig == 0)
                    srow[nwIdx * 128 + wm + im * 16 + gid + h * 8] = v;
            }
        }
        __syncthreads();
        if (tid < 128) {
            float t = srow[tid] + srow[128 + tid] + srow[256 + tid] + srow[384 + tid];
            spart[((size_t)bz * NN + m0 + tid) * 32 + blockIdx.x] = t;
        }
    }
}

// ---------------- launch ----------------
extern "C" void kernel_launch(void* const* d_in, const int* in_sizes, int n_in,
                              void* d_out, int out_size)
{
    const float* x     = (const float*)d_in[0];
    const float* gamma = (const float*)d_in[1];
    const float* beta  = (const float*)d_in[2];
    const float* wq    = (const float*)d_in[3];
    const float* bq    = (const float*)d_in[4];
    const float* wk    = (const float*)d_in[5];
    const float* bk    = (const float*)d_in[6];
    const float* wv    = (const float*)d_in[7];
    const float* bv    = (const float*)d_in[8];
    const float* wo    = (const float*)d_in[9];
    const float* bo    = (const float*)d_in[10];
    float* out = (float*)d_out;

    bf16 *h16, *qk16, *v16, *ao16, *e16, *w16;
    float *bqk, *spart;
    float2* part;
    cudaGetSymbolAddress((void**)&h16,  g_h16);
    cudaGetSymbolAddress((void**)&qk16, g_qk16);
    cudaGetSymbolAddress((void**)&v16,  g_v16);
    cudaGetSymbolAddress((void**)&ao16, g_ao16);
    cudaGetSymbolAddress((void**)&e16,  g_e16);
    cudaGetSymbolAddress((void**)&w16,  g_w16);
    cudaGetSymbolAddress((void**)&bqk,  g_bqk);
    cudaGetSymbolAddress((void**)&spart, g_spart);
    cudaGetSymbolAddress((void**)&part, g_part);

    static bool attr_done = false;
    if (!attr_done) {
        cudaFuncSetAttribute(mma_gemm<0>, cudaFuncAttributeMaxDynamicSharedMemorySize, SMEM_REQ);
        cudaFuncSetAttribute(mma_gemm<1>, cudaFuncAttributeMaxDynamicSharedMemorySize, SMEM_REQ);
        cudaFuncSetAttribute(mma_gemm<2>, cudaFuncAttributeMaxDynamicSharedMemorySize, SMEM_REQ);
        cudaFuncSetAttribute(mma_gemm<3>, cudaFuncAttributeMaxDynamicSharedMemorySize, SMEM_REQ);
        cudaFuncSetAttribute(mma_gemm<4>, cudaFuncAttributeMaxDynamicSharedMemorySize, SMEM_REQ);
        attr_done = true;
    }

    const long CN  = (long)Cc * NN;
    const long NC  = (long)NN * Cc;
    const long NC2 = (long)NN * 2 * Cc;
    const long NN2 = (long)NN * NN;
    const float scale = 1.0f / sqrtf((float)Cc);

    cudaLaunchAttribute pdl[1];
    pdl[0].id = cudaLaunchAttributeProgrammaticStreamSerialization;
    pdl[0].val.programmaticStreamSerializationAllowed = 1;

    // 1) prep first (depends only on inputs)
    prep_kernel<<<4 * Cc * Cc / 256, 256>>>(wq, wk, wv, wo, w16, bq, bk, bqk);

    // 2) gn_stats — independent of prep, PDL (no wait): drain-fill overlap
    {
        cudaLaunchConfig_t cfg = {};
        cfg.gridDim = dim3(Bb * GG * 8);
        cfg.blockDim = dim3(256);
        cfg.stream = 0;
        cfg.attrs = pdl; cfg.numAttrs = 1;
        cudaLaunchKernelEx(&cfg, gn_stats, x, part);
    }

    // 3) gn_norm — depends on gn_stats, PDL + in-kernel gdc_wait
    {
        cudaLaunchConfig_t cfg = {};
        cfg.gridDim = dim3(Bb * GG * 8);
        cfg.blockDim = dim3(256);
        cfg.stream = 0;
        cfg.attrs = pdl; cfg.numAttrs = 1;
        cudaLaunchKernelEx(&cfg, gn_norm, x, (const float2*)part, gamma, beta, h16);
    }

    // 4) merged QK proj — multi-predecessor (gn_norm + prep): normal launch
    mma_gemm<0><<<dim3(2*Cc/BN, NN/BM, Bb), 256, SMEM_REQ>>>(
        h16, NC, Cc, w16, 0, Cc, bqk, 0, nullptr, 0, nullptr, qk16, NC2, 2*Cc, Cc, 0.f);

    // 5) V proj — independent of QK proj: PDL (no wait)
    {
        cudaLaunchConfig_t cfg = {};
        cfg.gridDim = dim3(NN/BN, Cc/BM, Bb);
        cfg.blockDim = dim3(256);
        cfg.dynamicSmemBytes = SMEM_REQ;
        cfg.stream = 0;
        cfg.attrs = pdl; cfg.numAttrs = 1;
        cudaLaunchKernelEx(&cfg, mma_gemm<1>,
            (const bf16*)(w16 + 2*Cc*Cc), 0L, (int)Cc,
            (const bf16*)h16, NC, (int)Cc,
            bv, 0L, (const float*)nullptr, 0L, (float*)nullptr,
            (void*)v16, CN, (int)NN, (int)Cc, 0.f);
    }

    // 6) exp-scores — depends on gemm0 two launches back: normal launch
    mma_gemm<2><<<dim3(NN/BN, NN/BM, Bb), 256, SMEM_REQ>>>(
        qk16, NC2, 2*Cc, qk16 + Cc, NC2, 2*Cc, nullptr, 0, nullptr, 0, spart, e16, NN2, NN, Cc, scale);

    // 7) attn*V — single predecessor (gemm2): PDL + in-kernel gdc_wait
    {
        cudaLaunchConfig_t cfg = {};
        cfg.gridDim = dim3(Cc/BN, NN/BM, Bb);
        cfg.blockDim = dim3(256);
        cfg.dynamicSmemBytes = SMEM_REQ;
        cfg.stream = 0;
        cfg.attrs = pdl; cfg.numAttrs = 1;
        cudaLaunchKernelEx(&cfg, mma_gemm<3>,
            (const bf16*)e16, NN2, (int)NN,
            (const bf16*)v16, CN, (int)NN,
            (const float*)nullptr, 0L, (const float*)nullptr, 0L, spart,
            (void*)ao16, NC, (int)Cc, (int)NN, 0.f);
    }

    // 8) output proj + residual — single predecessor (gemm3): PDL + gdc_wait
    {
        cudaLaunchConfig_t cfg = {};
        cfg.gridDim = dim3(NN/BN, Cc/BM, Bb);
        cfg.blockDim = dim3(256);
        cfg.dynamicSmemBytes = SMEM_REQ;
        cfg.stream = 0;
        cfg.attrs = pdl; cfg.numAttrs = 1;
        cudaLaunchKernelEx(&cfg, mma_gemm<4>,
            (const bf16*)(w16 + 3*Cc*Cc), 0L, (int)Cc,
            (const bf16*)ao16, NC, (int)Cc,
            bo, 0L, x, CN, (float*)nullptr,
            (void*)out, CN, (int)NN, (int)Cc, 0.f);
    }
}

// round 17
// speedup vs baseline: 1.0029x; 1.0002x over previous
#include <cuda_runtime.h>
#include <cuda_bf16.h>
#include <math.h>
#include <stdint.h>

typedef __nv_bfloat16 bf16;
typedef __nv_bfloat162 bf162;

// ---------------- problem constants ----------------
#define Bb 4
#define Cc 512
#define NN 4096
#define GG 32
#define CPG 16

// ---------------- scratch (device globals) ----------------
__device__ __align__(128) bf16  g_h16  [(size_t)Bb*NN*Cc];    // [B,N,C] GN out
__device__ __align__(128) bf16  g_qk16 [(size_t)Bb*NN*2*Cc];  // [B,N,2C] q|k
__device__ __align__(128) bf16  g_v16  [(size_t)Bb*Cc*NN];    // [B,C,N]
__device__ __align__(128) bf16  g_ao16 [(size_t)Bb*NN*Cc];    // [B,N,C]
__device__ __align__(128) bf16  g_e16  [(size_t)Bb*NN*NN];    // [B,N,N] exp(scores)
__device__ __align__(128) bf16  g_w16  [4*Cc*Cc];             // wq|wk|wv|wo
__device__ __align__(128) float g_bqk  [2*Cc];                // bq|bk
__device__ __align__(128) float g_spart[(size_t)Bb*NN*32];    // per-CTA row partials
__device__ __align__(128) float2 g_part[Bb*GG*8];             // GN partials

// ---------------- helpers ----------------
__device__ __forceinline__ uint32_t smem_u32(const void* p) {
    uint32_t a;
    asm("{ .reg .u64 t; cvta.to.shared.u64 t, %1; cvt.u32.u64 %0, t; }" : "=r"(a) : "l"(p));
    return a;
}
__device__ __forceinline__ void gdc_wait() {
    asm volatile("griddepcontrol.wait;" ::: "memory");
}
__device__ __forceinline__ void mma_bf16(float* c, const uint32_t* a, const uint32_t* b) {
    asm volatile("mma.sync.aligned.m16n8k16.row.col.f32.bf16.bf16.f32 "
        "{%0,%1,%2,%3}, {%4,%5,%6,%7}, {%8,%9}, {%0,%1,%2,%3};"
        : "+f"(c[0]), "+f"(c[1]), "+f"(c[2]), "+f"(c[3])
        : "r"(a[0]), "r"(a[1]), "r"(a[2]), "r"(a[3]), "r"(b[0]), "r"(b[1]));
}
__device__ __forceinline__ void ldmatrix_x4(uint32_t* r, uint32_t addr) {
    asm volatile("ldmatrix.sync.aligned.m8n8.x4.shared.b16 {%0,%1,%2,%3}, [%4];"
        : "=r"(r[0]), "=r"(r[1]), "=r"(r[2]), "=r"(r[3]) : "r"(addr));
}

// ---------------- block reduction ----------------
__device__ __forceinline__ float block_sum(float v, float* sh) {
    int lane = threadIdx.x & 31, w = threadIdx.x >> 5;
    #pragma unroll
    for (int o = 16; o; o >>= 1) v += __shfl_down_sync(0xffffffffu, v, o);
    if (!lane) sh[w] = v;
    __syncthreads();
    int nw = blockDim.x >> 5;
    v = (threadIdx.x < nw) ? sh[threadIdx.x] : 0.f;
    if (w == 0) {
        #pragma unroll
        for (int o = 16; o; o >>= 1) v += __shfl_down_sync(0xffffffffu, v, o);
        if (!lane) sh[0] = v;
    }
    __syncthreads();
    float r = sh[0]; __syncthreads(); return r;
}

// ---------------- GroupNorm stage 1 --------------------------
__global__ __launch_bounds__(256) void gn_stats(
    const float* __restrict__ x, float2* __restrict__ partials)
{
    __shared__ float sh[32];
    int blk = blockIdx.x;
    int bg = blk >> 3, p = blk & 7;
    const size_t base = (size_t)bg * CPG * NN;
    const int i0 = p * 512;

    float s = 0.f, ss = 0.f;
    #pragma unroll
    for (int c = 0; c < CPG; c++) {
        #pragma unroll
        for (int j = 0; j < 2; j++) {
            float v = x[base + (size_t)c * NN + i0 + threadIdx.x + j * 256];
            s += v; ss += v * v;
        }
    }
    s  = block_sum(s,  sh);
    ss = block_sum(ss, sh);
    if (threadIdx.x == 0) partials[blk] = make_float2(s, ss);
}

// ---------------- GroupNorm stage 2 (PDL: waits on gn_stats) ----------------
__global__ __launch_bounds__(256) void gn_norm(
    const float* __restrict__ x, const float2* __restrict__ partials,
    const float* __restrict__ gamma, const float* __restrict__ beta,
    bf16* __restrict__ hT)
{
    gdc_wait();

    int blk = blockIdx.x;
    int bg = blk >> 3, p = blk & 7;
    int b = bg / GG, g = bg % GG;

    float s = 0.f, ss = 0.f;
    #pragma unroll
    for (int q = 0; q < 8; q++) {
        float2 pr = partials[bg * 8 + q];
        s += pr.x; ss += pr.y;
    }
    const float len = (float)(CPG * NN);
    float mean = s / len;
    float inv  = rsqrtf(ss / len - mean * mean + 1e-6f);

    float gm[CPG], bt[CPG];
    #pragma unroll
    for (int c = 0; c < CPG; c++) { gm[c] = gamma[g*CPG+c] * inv; bt[c] = beta[g*CPG+c]; }

    const size_t base = (size_t)bg * CPG * NN;
    #pragma unroll
    for (int j = 0; j < 2; j++) {
        int i = p * 512 + threadIdx.x + j * 256;
        bf162 vals[CPG/2];
        #pragma unroll
        for (int c = 0; c < CPG; c += 2) {
            float a  = (x[base + (size_t)c     * NN + i] - mean) * gm[c]   + bt[c];
            float b2 = (x[base + (size_t)(c+1) * NN + i] - mean) * gm[c+1] + bt[c+1];
            vals[c/2] = __floats2bfloat162_rn(a, b2);
        }
        bf16* dst = hT + ((size_t)b * NN + i) * Cc + g * CPG;
        #pragma unroll
        for (int q = 0; q < CPG/8; q++)
            ((float4*)dst)[q] = *(float4*)&vals[q*4];
    }
}

// ---------------- weight convert (vectorized) + bias concat ----------------
// 4*Cc*Cc = 2^20 floats; each thread converts 8 via two float4 loads.
__global__ __launch_bounds__(256) void prep_kernel(
    const float* __restrict__ a, const float* __restrict__ b,
    const float* __restrict__ c, const float* __restrict__ d,
    bf16* __restrict__ o,
    const float* __restrict__ bq, const float* __restrict__ bk,
    float* __restrict__ bqk)
{
    int t = blockIdx.x * 256 + threadIdx.x;      // 2^17 threads
    int i = t * 8;                               // element base
    int w = i >> 18, j = i & 0x3FFFF;
    const float* src = (w == 0) ? a : (w == 1) ? b : (w == 2) ? c : d;
    float4 f0 = *(const float4*)(src + j);
    float4 f1 = *(const float4*)(src + j + 4);
    bf162 h[4];
    h[0] = __floats2bfloat162_rn(f0.x, f0.y);
    h[1] = __floats2bfloat162_rn(f0.z, f0.w);
    h[2] = __floats2bfloat162_rn(f1.x, f1.y);
    h[3] = __floats2bfloat162_rn(f1.z, f1.w);
    *(uint4*)(o + i) = *(uint4*)h;
    if (t < 2 * Cc) bqk[t] = (t < Cc) ? bq[t] : bk[t - Cc];
}

// ---------------- bf16 mma.sync GEMM ----------
// EPI: 0 = +bias[n] -> bf16       (merged QK proj)
//      1 = +bias[m] -> bf16       (V proj)
//      2 = exp(v*alpha) -> bf16 + per-CTA row partials -> spart (scores)
//      3 = *invsum[m] -> bf16     (attn*V; invsum computed in-kernel; PDL wait)
//      4 = +bias[m]+res fp32      (output proj + residual; PDL wait)
#define BM 128
#define BN 128
#define BK 64
#define STAGES 3
#define SROW 72
#define ATILE_H (BM * SROW)
#define BTILE_H (BN * SROW)
#define STAGE_H (ATILE_H + BTILE_H)
#define STAGE_BYTES (STAGE_H * 2)
#define SMEM_REQ (STAGES * STAGE_BYTES + 512)

template<int ROWS>
__device__ __forceinline__ void load_tile(const bf16* g, bf16* s, int tid, int ld) {
    int ch = tid & 7;
    int r0 = tid >> 3;
    #pragma unroll
    for (int i = 0; i < ROWS / 32; i++) {
        int r = r0 + i * 32;
        uint32_t dst = smem_u32(s + r * SROW + ch * 8);
        const bf16* src = g + (size_t)r * ld + ch * 8;
        asm volatile("cp.async.cg.shared.global [%0], [%1], 16;" :: "r"(dst), "l"(src));
    }
}

template<int EPI>
__global__ __launch_bounds__(256, 2) void mma_gemm(
    const bf16* __restrict__ A, long zA, int ldA,
    const bf16* __restrict__ B, long zB, int ldB,
    const float* __restrict__ bias, long zBias,
    const float* __restrict__ res, long zR,
    float* __restrict__ spart,
    void* __restrict__ Cout, long zC, int ldC,
    int K, float alpha)
{
    constexpr bool OUT_BF = (EPI != 4);
    extern __shared__ bf16 smem[];
    float* srsum = (float*)(smem + STAGES * STAGE_H);

    if (EPI == 3 || EPI == 4) gdc_wait();

    const int tid = threadIdx.x;
    const int m0 = blockIdx.y * BM, n0 = blockIdx.x * BN, bz = blockIdx.z;

    A += (size_t)bz * zA + (size_t)m0 * ldA;
    B += (size_t)bz * zB + (size_t)n0 * ldB;
    if (EPI == 1 || EPI == 4) bias += (size_t)bz * zBias;

    const int KT = K / BK;

    #pragma unroll
    for (int st = 0; st < STAGES - 1; st++) {
        load_tile<BM>(A + st * BK, smem + st * STAGE_H, tid, ldA);
        load_tile<BN>(B + st * BK, smem + st * STAGE_H + ATILE_H, tid, ldB);
        asm volatile("cp.async.commit_group;" ::: "memory");
    }

    if (EPI == 3) {
        if (tid < 128) {
            const float* p = spart + ((size_t)bz * NN + m0 + tid) * 32;
            float s = 0.f;
            #pragma unroll
            for (int t = 0; t < 32; t++) s += p[t];
            srsum[tid] = 1.f / s;
        }
    }

    const int lane = tid & 31, wid = tid >> 5;
    const int gid = lane >> 2, tig = lane & 3;
    const int wm = (wid & 1) * 64;
    const int wn = (wid >> 1) * 32;

    const uint32_t sbase = smem_u32(smem);
    const uint32_t a_off = ((wm + (lane & 15)) * SROW + ((lane >> 4) * 8)) * 2;
    const uint32_t b_off = (ATILE_H + (wn + (lane & 7) + ((lane >> 4) << 3)) * SROW
                            + (((lane >> 3) & 1) * 8)) * 2;

    float c[4][4][4];
    #pragma unroll
    for (int im = 0; im < 4; im++)
        #pragma unroll
        for (int in = 0; in < 4; in++)
            #pragma unroll
            for (int r = 0; r < 4; r++) c[im][in][r] = 0.f;

    uint32_t af[2][4][4], bq[2][2][4];

    for (int kt = 0; kt < KT; kt++) {
        asm volatile("cp.async.wait_group %0;" :: "n"(STAGES - 2) : "memory");
        __syncthreads();

        if (kt + STAGES - 1 < KT) {
            int st = (kt + STAGES - 1) % STAGES;
            load_tile<BM>(A + (kt + STAGES - 1) * BK, smem + st * STAGE_H, tid, ldA);
            load_tile<BN>(B + (kt + STAGES - 1) * BK, smem + st * STAGE_H + ATILE_H, tid, ldB);
        }
        asm volatile("cp.async.commit_group;" ::: "memory");

        const uint32_t stb = sbase + (kt % STAGES) * STAGE_BYTES;

        #pragma unroll
        for (int im = 0; im < 4; im++)
            ldmatrix_x4(af[0][im], stb + a_off + im * (16 * SROW * 2));
        #pragma unroll
        for (int ib = 0; ib < 2; ib++)
            ldmatrix_x4(bq[0][ib], stb + b_off + ib * (16 * SROW * 2));

        #pragma unroll
        for (int kk = 0; kk < 4; kk++) {
            int cur = kk & 1, nxt = cur ^ 1;
            if (kk < 3) {
                const uint32_t ka = stb + (kk + 1) * 32;
                #pragma unroll
                for (int im = 0; im < 4; im++)
                    ldmatrix_x4(af[nxt][im], ka + a_off + im * (16 * SROW * 2));
                #pragma unroll
                for (int ib = 0; ib < 2; ib++)
                    ldmatrix_x4(bq[nxt][ib], ka + b_off + ib * (16 * SROW * 2));
            }
            #pragma unroll
            for (int im = 0; im < 4; im++)
                #pragma unroll
                for (int in = 0; in < 4; in++)
                    mma_bf16(c[im][in], af[cur][im], &bq[cur][in >> 1][(in & 1) * 2]);
        }
    }

    // ---- epilogue ----
    float rs[4][2];
    if (EPI == 2) {
        #pragma unroll
        for (int im = 0; im < 4; im++) { rs[im][0] = 0.f; rs[im][1] = 0.f; }
    }

    #pragma unroll
    for (int im = 0; im < 4; im++) {
        int r0 = im * 16 + gid;
        float bm0 = 0.f, bm1 = 0.f;
        if (EPI == 1 || EPI == 4) {
            bm0 = __ldg(bias + m0 + wm + r0);
            bm1 = __ldg(bias + m0 + wm + r0 + 8);
        } else if (EPI == 3) {
            bm0 = srsum[wm + r0];
            bm1 = srsum[wm + r0 + 8];
        }
        #pragma unroll
        for (int in = 0; in < 4; in++) {
            int col = in * 8 + tig * 2;
            float v0 = c[im][in][0], v1 = c[im][in][1];
            float v2 = c[im][in][2], v3 = c[im][in][3];
            if (EPI == 0) {
                float bn0 = __ldg(bias + n0 + wn + col);
                float bn1 = __ldg(bias + n0 + wn + col + 1);
                v0 += bn0; v1 += bn1; v2 += bn0; v3 += bn1;
            } else if (EPI == 1) {
                v0 += bm0; v1 += bm0; v2 += bm1; v3 += bm1;
            } else if (EPI == 2) {
                v0 = __expf(v0 * alpha); v1 = __expf(v1 * alpha);
                v2 = __expf(v2 * alpha); v3 = __expf(v3 * alpha);
                rs[im][0] += v0 + v1;
                rs[im][1] += v2 + v3;
            } else if (EPI == 3) {
                v0 *= bm0; v1 *= bm0; v2 *= bm1; v3 *= bm1;
            } else if (EPI == 4) {
                const float* ra = res + (size_t)bz * zR + (size_t)(m0 + wm + r0) * ldC + n0 + wn + col;
                const float* rb = res + (size_t)bz * zR + (size_t)(m0 + wm + r0 + 8) * ldC + n0 + wn + col;
                v0 += bm0 + ra[0]; v1 += bm0 + ra[1];
                v2 += bm1 + rb[0]; v3 += bm1 + rb[1];
            }
            if (OUT_BF) {
                bf16* Cb = (bf16*)Cout + (size_t)bz * zC + (size_t)(m0 + wm + r0) * ldC + n0 + wn + col;
                bf16* Cb2 = (bf16*)Cout + (size_t)bz * zC + (size_t)(m0 + wm + r0 + 8) * ldC + n0 + wn + col;
                *(bf162*)Cb  = __floats2bfloat162_rn(v0, v1);
                *(bf162*)Cb2 = __floats2bfloat162_rn(v2, v3);
            } else {
                float* Cf = (float*)Cout + (size_t)bz * zC + (size_t)(m0 + wm + r0) * ldC + n0 + wn + col;
                float* Cf2 = (float*)Cout + (size_t)bz * zC + (size_t)(m0 + wm + r0 + 8) * ldC + n0 + wn + col;
                *(float2*)Cf  = make_float2(v0, v1);
                *(float2*)Cf2 = make_float2(v2, v3);
            }
        }
    }

    // ---- EPI2: deterministic per-CTA row-sum reduction -> spart ----
    if (EPI == 2) {
        __syncthreads();
        float* srow = (float*)smem;
        const int nwIdx = wid >> 1;
        #pragma unroll
        for (int im = 0; im < 4; im++) {
            #pragma unroll
            for (int h = 0; h < 2; h++) {
                float v = rs[im][h];
                v += __shfl_xor_sync(0xffffffffu, v, 1);
                v += __shfl_xor_sync(0xffffffffu, v, 2);
                if (tig == 0)
                    srow[nwIdx * 128 + wm + im * 16 + gid + h * 8] = v;
            }
        }
        __syncthreads();
        if (tid < 128) {
            float t = srow[tid] + srow[128 + tid] + srow[256 + tid] + srow[384 + tid];
            spart[((size_t)bz * NN + m0 + tid) * 32 + blockIdx.x] = t;
        }
    }
}

// ---------------- launch ----------------
extern "C" void kernel_launch(void* const* d_in, const int* in_sizes, int n_in,
                              void* d_out, int out_size)
{
    const float* x     = (const float*)d_in[0];
    const float* gamma = (const float*)d_in[1];
    const float* beta  = (const float*)d_in[2];
    const float* wq    = (const float*)d_in[3];
    const float* bq    = (const float*)d_in[4];
    const float* wk    = (const float*)d_in[5];
    const float* bk    = (const float*)d_in[6];
    const float* wv    = (const float*)d_in[7];
    const float* bv    = (const float*)d_in[8];
    const float* wo    = (const float*)d_in[9];
    const float* bo    = (const float*)d_in[10];
    float* out = (float*)d_out;

    bf16 *h16, *qk16, *v16, *ao16, *e16, *w16;
    float *bqk, *spart;
    float2* part;
    cudaGetSymbolAddress((void**)&h16,  g_h16);
    cudaGetSymbolAddress((void**)&qk16, g_qk16);
    cudaGetSymbolAddress((void**)&v16,  g_v16);
    cudaGetSymbolAddress((void**)&ao16, g_ao16);
    cudaGetSymbolAddress((void**)&e16,  g_e16);
    cudaGetSymbolAddress((void**)&w16,  g_w16);
    cudaGetSymbolAddress((void**)&bqk,  g_bqk);
    cudaGetSymbolAddress((void**)&spart, g_spart);
    cudaGetSymbolAddress((void**)&part, g_part);

    static bool attr_done = false;
    if (!attr_done) {
        cudaFuncSetAttribute(mma_gemm<0>, cudaFuncAttributeMaxDynamicSharedMemorySize, SMEM_REQ);
        cudaFuncSetAttribute(mma_gemm<1>, cudaFuncAttributeMaxDynamicSharedMemorySize, SMEM_REQ);
        cudaFuncSetAttribute(mma_gemm<2>, cudaFuncAttributeMaxDynamicSharedMemorySize, SMEM_REQ);
        cudaFuncSetAttribute(mma_gemm<3>, cudaFuncAttributeMaxDynamicSharedMemorySize, SMEM_REQ);
        cudaFuncSetAttribute(mma_gemm<4>, cudaFuncAttributeMaxDynamicSharedMemorySize, SMEM_REQ);
        attr_done = true;
    }

    const long CN  = (long)Cc * NN;
    const long NC  = (long)NN * Cc;
    const long NC2 = (long)NN * 2 * Cc;
    const long NN2 = (long)NN * NN;
    const float scale = 1.0f / sqrtf((float)Cc);

    cudaLaunchAttribute pdl[1];
    pdl[0].id = cudaLaunchAttributeProgrammaticStreamSerialization;
    pdl[0].val.programmaticStreamSerializationAllowed = 1;

    // 1) prep first (depends only on inputs) — vectorized, 512 blocks
    prep_kernel<<<4 * Cc * Cc / (256 * 8), 256>>>(wq, wk, wv, wo, w16, bq, bk, bqk);

    // 2) gn_stats — independent of prep, PDL (no wait)
    {
        cudaLaunchConfig_t cfg = {};
        cfg.gridDim = dim3(Bb * GG * 8);
        cfg.blockDim = dim3(256);
        cfg.stream = 0;
        cfg.attrs = pdl; cfg.numAttrs = 1;
        cudaLaunchKernelEx(&cfg, gn_stats, x, part);
    }

    // 3) gn_norm — depends on gn_stats, PDL + in-kernel gdc_wait
    {
        cudaLaunchConfig_t cfg = {};
        cfg.gridDim = dim3(Bb * GG * 8);
        cfg.blockDim = dim3(256);
        cfg.stream = 0;
        cfg.attrs = pdl; cfg.numAttrs = 1;
        cudaLaunchKernelEx(&cfg, gn_norm, x, (const float2*)part, gamma, beta, h16);
    }

    // 4) merged QK proj — multi-predecessor: normal launch
    mma_gemm<0><<<dim3(2*Cc/BN, NN/BM, Bb), 256, SMEM_REQ>>>(
        h16, NC, Cc, w16, 0, Cc, bqk, 0, nullptr, 0, nullptr, qk16, NC2, 2*Cc, Cc, 0.f);

    // 5) V proj — independent of QK proj: PDL (no wait)
    {
        cudaLaunchConfig_t cfg = {};
        cfg.gridDim = dim3(NN/BN, Cc/BM, Bb);
        cfg.blockDim = dim3(256);
        cfg.dynamicSmemBytes = SMEM_REQ;
        cfg.stream = 0;
        cfg.attrs = pdl; cfg.numAttrs = 1;
        cudaLaunchKernelEx(&cfg, mma_gemm<1>,
            (const bf16*)(w16 + 2*Cc*Cc), 0L, (int)Cc,
            (const bf16*)h16, NC, (int)Cc,
            bv, 0L, (const float*)nullptr, 0L, (float*)nullptr,
            (void*)v16, CN, (int)NN, (int)Cc, 0.f);
    }

    // 6) exp-scores — depends on gemm0 two launches back: normal launch
    mma_gemm<2><<<dim3(NN/BN, NN/BM, Bb), 256, SMEM_REQ>>>(
        qk16, NC2, 2*Cc, qk16 + Cc, NC2, 2*Cc, nullptr, 0, nullptr, 0, spart, e16, NN2, NN, Cc, scale);

    // 7) attn*V — single predecessor (gemm2): PDL + in-kernel gdc_wait
    {
        cudaLaunchConfig_t cfg = {};
        cfg.gridDim = dim3(Cc/BN, NN/BM, Bb);
        cfg.blockDim = dim3(256);
        cfg.dynamicSmemBytes = SMEM_REQ;
        cfg.stream = 0;
        cfg.attrs = pdl; cfg.numAttrs = 1;
        cudaLaunchKernelEx(&cfg, mma_gemm<3>,
            (const bf16*)e16, NN2, (int)NN,
            (const bf16*)v16, CN, (int)NN,
            (const float*)nullptr, 0L, (const float*)nullptr, 0L, spart,
            (void*)ao16, NC, (int)Cc, (int)NN, 0.f);
    }

    // 8) output proj + residual — single predecessor (gemm3): PDL + gdc_wait
    {
        cudaLaunchConfig_t cfg = {};
        cfg.gridDim = dim3(NN/BN, Cc/BM, Bb);
        cfg.blockDim = dim3(256);
        cfg.dynamicSmemBytes = SMEM_REQ;
        cfg.stream = 0;
        cfg.attrs = pdl; cfg.numAttrs = 1;
        cudaLaunchKernelEx(&cfg, mma_gemm<4>,
            (const bf16*)(w16 + 3*Cc*Cc), 0L, (int)Cc,
            (const bf16*)ao16, NC, (int)Cc,
            bo, 0L, x, CN, (float*)nullptr,
            (void*)out, CN, (int)NN, (int)Cc, 0.f);
    }
}